// round 16
// baseline (speedup 1.0000x reference)
#include <cuda_runtime.h>
#include <cuda_bf16.h>
#include <cstdint>
#include <cstddef>

#define BATCH 32
#define DCH 256
#define NG 64
#define PPAD 1088   // padded total conv positions (17 * 64)

__constant__ int c_off[31] = {0,64,128,192,252,312,372,432,488,544,600,656,708,760,812,
                              864,888,912,936,960,980,1000,1020,
                              1040,1048,1056,1064,1072,1076,1080,1084};
__constant__ int c_tb[31]  = {0,2,4,6,8,10,12,14,16,18,20,22,24,26,28, 30,
                              33,35,37,39,41,43,45, 47, 50,52,54,56,58,60,62};
__constant__ int c_taps[31] = {2,2,2,2,2,2,2,2,2,2,2,2,2,2,2, 3, 2,2,2,2,2,2,2, 3,
                               2,2,2,2,2,2,2};
__constant__ int c_cs[31]   = {1,1,1,1,1,1,1,1,1,1,1,1,1,1,1, 2, 1,1,1,1,1,1,1, 2,
                               1,1,1,1,1,1,1};
__constant__ int c_M[31]    = {63,62,61,60,59,58,57,56,55,54,53,52,51,50,49, 24,
                               23,22,21,20,19,18,17, 8, 7,6,5,4,3,2,1};
__constant__ int c_bi[31]   = {0,1,2,3,4,5,6,7,8,9,10,11,12,13,14, 0,
                               15,16,17,18,19,20,21, 1, 22,23,24,25,26,27,28};
__constant__ int c_isk3[31] = {0,0,0,0,0,0,0,0,0,0,0,0,0,0,0, 1, 0,0,0,0,0,0,0, 1,
                               0,0,0,0,0,0,0};
__constant__ int c_tb2[29]  = {0,2,4,6,8,10,12,14,16,18,20,22,24,26,28,
                               33,35,37,39,41,43,45, 50,52,54,56,58,60,62};

// ---------------- scratch ----------------
__device__ float g_Pc[(size_t)BATCH * PPAD * DCH];
__device__ float g_P[(size_t)BATCH * NG * 768];
__device__ uint4 g_act_hi[(size_t)BATCH * PPAD * 256 / 8];
__device__ uint4 g_act_lo[(size_t)BATCH * PPAD * 256 / 8];
__device__ uint4 g_xa_hi[(size_t)BATCH * 64 * 256 / 8];
__device__ uint4 g_xa_lo[(size_t)BATCH * 64 * 256 / 8];
__device__ uint4 g_w_hi[64 * 256 * 256 / 8];
__device__ uint4 g_w_lo[64 * 256 * 256 / 8];
__device__ uint4 g_wB_hi[768 * 256 / 8];
__device__ uint4 g_wB_lo[768 * 256 / 8];

// ---------------- helpers ----------------
__device__ __forceinline__ void cluster_sync_all() {
    asm volatile("barrier.cluster.arrive.aligned;" ::: "memory");
    asm volatile("barrier.cluster.wait.aligned;" ::: "memory");
}
__device__ __forceinline__ uint32_t smem_u32(const void* p) {
    uint32_t a;
    asm("{ .reg .u64 t; cvta.to.shared.u64 t, %1; cvt.u32.u64 %0, t; }"
        : "=r"(a) : "l"(p));
    return a;
}
__device__ __forceinline__ void mma_bf16(float* d, const uint32_t* a,
                                         const uint32_t* b) {
    asm volatile(
        "mma.sync.aligned.m16n8k16.row.col.f32.bf16.bf16.f32 "
        "{%0,%1,%2,%3}, {%4,%5,%6,%7}, {%8,%9}, {%0,%1,%2,%3};"
        : "+f"(d[0]), "+f"(d[1]), "+f"(d[2]), "+f"(d[3])
        : "r"(a[0]), "r"(a[1]), "r"(a[2]), "r"(a[3]), "r"(b[0]), "r"(b[1]));
}
__device__ __forceinline__ void ldsm_x4(uint32_t& r0, uint32_t& r1, uint32_t& r2,
                                        uint32_t& r3, uint32_t a) {
    asm volatile("ldmatrix.sync.aligned.m8n8.x4.shared.b16 {%0,%1,%2,%3}, [%4];"
                 : "=r"(r0), "=r"(r1), "=r"(r2), "=r"(r3) : "r"(a));
}
__device__ __forceinline__ void cp16(uint32_t s, const void* g) {
    asm volatile("cp.async.cg.shared.global [%0], [%1], 16;" :: "r"(s), "l"(g)
                 : "memory");
}
#define CP_COMMIT() asm volatile("cp.async.commit_group;" ::: "memory")
#define CP_WAIT0() asm volatile("cp.async.wait_group 0;" ::: "memory")
#define CP_WAIT1() asm volatile("cp.async.wait_group 1;" ::: "memory")

// ---------------- x -> xact split ----------------
__global__ void xsplit(const float* __restrict__ x,
                       __nv_bfloat16* __restrict__ hi,
                       __nv_bfloat16* __restrict__ lo) {
    __shared__ float t[32][33];
    int b = blockIdx.z;
    int p0 = blockIdx.x * 32, ch0 = blockIdx.y * 32;
    int tx = threadIdx.x, ty = threadIdx.y;
#pragma unroll
    for (int s = 0; s < 32; s += 8) {
        int c = ch0 + ty + s;
        t[ty + s][tx] = x[((size_t)b * DCH + c) * NG + p0 + tx];
    }
    __syncthreads();
#pragma unroll
    for (int s = 0; s < 32; s += 8) {
        int p = p0 + ty + s, c = ch0 + tx;
        float v = t[tx][ty + s];
        __nv_bfloat16 h = __float2bfloat16(v);
        __nv_bfloat16 l = __float2bfloat16(v - __bfloat162float(h));
        size_t o = ((size_t)b * NG + p) * 256 + c;
        hi[o] = h;
        lo[o] = l;
    }
}

// ---------------- weight split (w2/w3 per-tap + full vis_w merged) ----------------
#define W2TOT (29 * 256 * 256 * 2)
#define W3END (W2TOT + 2 * 256 * 256 * 3)
#define VWTOT (768 * 256)
#define PREP_TOT (W3END + VWTOT)
__global__ void wsplit(const float* __restrict__ w2, const float* __restrict__ w3,
                       const float* __restrict__ vw,
                       __nv_bfloat16* __restrict__ hi,
                       __nv_bfloat16* __restrict__ lo,
                       __nv_bfloat16* __restrict__ vhi,
                       __nv_bfloat16* __restrict__ vlo) {
    for (int idx = blockIdx.x * blockDim.x + threadIdx.x; idx < PREP_TOT;
         idx += gridDim.x * blockDim.x) {
        if (idx < W3END) {
            float v;
            int tap, n, c;
            if (idx < W2TOT) {
                int i2 = idx >> 17;
                int r = idx & 0x1FFFF;
                n = r >> 9;
                int r2 = r & 511;
                c = r2 >> 1;
                int kk = r2 & 1;
                v = w2[idx];
                tap = c_tb2[i2] + kk;
            } else {
                int j = idx - W2TOT;
                int i3 = j / 196608;
                int r = j % 196608;
                n = r / 768;
                int r2 = r % 768;
                c = r2 / 3;
                int kk = r2 % 3;
                v = w3[j];
                tap = (i3 ? 47 : 30) + kk;
            }
            size_t dst = (size_t)tap * 65536 + (size_t)n * 256 + c;
            __nv_bfloat16 h = __float2bfloat16(v);
            __nv_bfloat16 l = __float2bfloat16(v - __bfloat162float(h));
            hi[dst] = h;
            lo[dst] = l;
        } else {
            int j = idx - W3END;          // vis_w: row r = s*256+o, col c
            int r = j >> 8, c = j & 255;
            int o = r & 255, s = r >> 8;
            float v = vw[(size_t)o * 768 + s * 256 + c];
            __nv_bfloat16 h = __float2bfloat16(v);
            __nv_bfloat16 l = __float2bfloat16(v - __bfloat162float(h));
            vhi[(size_t)r * 256 + c] = h;
            vlo[(size_t)r * 256 + c] = l;
        }
    }
}

// ---------------- fused chain (R12 proven: 256 thr, 4-CTA cluster) ----------------
#define CROWB 528
#define CBUF (64 * CROWB)       // 33792 bytes
#define CH_SMEM (6 * CBUF)      // AH | AL | BH0 | BL0 | BH1 | BL1

__global__ void __launch_bounds__(256, 1) __cluster_dims__(4, 1, 1)
chain_mma(const uint4* __restrict__ xaH, const uint4* __restrict__ xaL,
          const uint4* __restrict__ gwH, const uint4* __restrict__ gwL,
          const float* __restrict__ b2, const float* __restrict__ b3,
          __nv_bfloat16* __restrict__ actH, __nv_bfloat16* __restrict__ actL) {
    extern __shared__ char sm[];
    uint32_t sb = smem_u32(sm);
    const uint32_t AHs = sb, ALs = sb + CBUF;
    const uint32_t BH0 = sb + 2 * CBUF, BL0 = sb + 3 * CBUF;
    const uint32_t BH1 = sb + 4 * CBUF, BL1 = sb + 5 * CBUF;

    int tid = threadIdx.x;
    int warp = tid >> 5, lane = tid & 31;
    int g = lane >> 2, t = lane & 3;
    int ridx = lane & 15, half = lane >> 4;
    int wm = (warp & 3) * 16;
    int wn = (warp >> 2) * 32;
    int b = blockIdx.x >> 2;
    int nblk = (blockIdx.x & 3) * 64;
    int lr = tid >> 5;
    int lq = tid & 31;

    const uint4* act4H = (const uint4*)actH;
    const uint4* act4L = (const uint4*)actL;

    uint32_t roff0 = (wn + ridx) * CROWB + half * 16;
    uint32_t roff1 = (wn + 16 + ridx) * CROWB + half * 16;

    auto load_B = [&](int tap, uint32_t BHb, uint32_t BLb) {
        size_t wb = (size_t)tap * 8192 + (size_t)nblk * 32;
#pragma unroll
        for (int i = 0; i < 8; i++) {
            int r = lr + 8 * i;
            uint32_t dst = r * CROWB + lq * 16;
            cp16(BHb + dst, &gwH[wb + (size_t)r * 32 + lq]);
            cp16(BLb + dst, &gwL[wb + (size_t)r * 32 + lq]);
        }
    };

    // preload layer-0 weights
    load_B(0, BH0, BL0);
    load_B(1, BH1, BL1);
    CP_COMMIT();

#pragma unroll 1
    for (int l = 0; l < 31; l++) {
        int taps = c_taps[l], cs = c_cs[l], tb = c_tb[l], M = c_M[l];
        int in_off = (l == 0) ? 0 : c_off[l - 1];
        int out_off = c_off[l];
        const float* bias = c_isk3[l] ? (b3 + c_bi[l] * 256) : (b2 + c_bi[l] * 256);

        if (l == 0) {
            size_t base = (size_t)b * 64 * 32;
#pragma unroll
            for (int i = 0; i < 8; i++) {
                int r = lr + 8 * i;
                uint32_t dst = r * CROWB + lq * 16;
                cp16(AHs + dst, &xaH[base + (size_t)r * 32 + lq]);
                cp16(ALs + dst, &xaL[base + (size_t)r * 32 + lq]);
            }
        } else {
#pragma unroll
            for (int i = 0; i < 8; i++) {
                int r = lr + 8 * i;
                int rr = in_off + r;
                if (rr > PPAD - 1) rr = PPAD - 1;
                size_t src = ((size_t)b * PPAD + rr) * 32 + lq;
                uint32_t dst = r * CROWB + lq * 16;
                cp16(AHs + dst, &act4H[src]);
                cp16(ALs + dst, &act4L[src]);
            }
        }
        CP_COMMIT();

        float acc[4][4];
#pragma unroll
        for (int ni = 0; ni < 4; ni++)
#pragma unroll
            for (int p = 0; p < 4; p++) acc[ni][p] = 0.f;

        bool active = (wm < M);

        auto mma_tap = [&](int tap, uint32_t BHb, uint32_t BLb) {
            int arow = ((wm + ridx) * cs + tap) & 63;
            uint32_t aHb = AHs + arow * CROWB + half * 16;
            uint32_t aLb = ALs + arow * CROWB + half * 16;
            uint32_t bh0 = BHb + roff0, bh1 = BHb + roff1;
            uint32_t bl0 = BLb + roff0, bl1 = BLb + roff1;
#pragma unroll
            for (int ks = 0; ks < 16; ks++) {
                uint32_t o = ks * 32;
                uint32_t ah[4], al[4];
                ldsm_x4(ah[0], ah[1], ah[2], ah[3], aHb + o);
                ldsm_x4(al[0], al[1], al[2], al[3], aLb + o);
                uint32_t p0, p1, p2, p3, q0, q1, q2, q3;
                ldsm_x4(p0, p1, p2, p3, bh0 + o);
                ldsm_x4(q0, q1, q2, q3, bh1 + o);
                uint32_t r0, r1, r2, r3, s0, s1, s2, s3;
                ldsm_x4(r0, r1, r2, r3, bl0 + o);
                ldsm_x4(s0, s1, s2, s3, bl1 + o);
                uint32_t fh0[2] = {p0, p2}, fh1[2] = {p1, p3};
                uint32_t fh2[2] = {q0, q2}, fh3[2] = {q1, q3};
                uint32_t fl0[2] = {r0, r2}, fl1[2] = {r1, r3};
                uint32_t fl2[2] = {s0, s2}, fl3[2] = {s1, s3};
                mma_bf16(acc[0], ah, fh0);
                mma_bf16(acc[1], ah, fh1);
                mma_bf16(acc[2], ah, fh2);
                mma_bf16(acc[3], ah, fh3);
                mma_bf16(acc[0], al, fh0);
                mma_bf16(acc[1], al, fh1);
                mma_bf16(acc[2], al, fh2);
                mma_bf16(acc[3], al, fh3);
                mma_bf16(acc[0], ah, fl0);
                mma_bf16(acc[1], ah, fl1);
                mma_bf16(acc[2], ah, fl2);
                mma_bf16(acc[3], ah, fl3);
            }
        };

        CP_WAIT0();
        __syncthreads();
        if (active) mma_tap(0, BH0, BL0);

        if (taps == 3) {
            __syncthreads();
            load_B(tb + 2, BH0, BL0);
            CP_COMMIT();
            if (active) mma_tap(1, BH1, BL1);
            CP_WAIT0();
            __syncthreads();
            if (active) mma_tap(2, BH0, BL0);
        } else {
            if (active) mma_tap(1, BH1, BL1);
        }

        __syncthreads();  // all B reads done -> buffers free
        if (l < 30) {     // prefetch next layer's weights (independent of sync)
            load_B(c_tb[l + 1], BH0, BL0);
            load_B(c_tb[l + 1] + 1, BH1, BL1);
            CP_COMMIT();
        }

        // epilogue
        int m0g = wm + g;
#pragma unroll
        for (int ni = 0; ni < 4; ni++) {
            int n = nblk + wn + ni * 8 + 2 * t;
            float bv0 = __ldg(bias + n);
            float bv1 = __ldg(bias + n + 1);
            if (m0g < M) {
                float v0 = acc[ni][0] + bv0, v1 = acc[ni][1] + bv1;
                size_t o = ((size_t)b * PPAD + out_off + m0g) * 256 + n;
                __nv_bfloat162 hh, ll;
                hh.x = __float2bfloat16(v0);
                hh.y = __float2bfloat16(v1);
                ll.x = __float2bfloat16(v0 - __bfloat162float(hh.x));
                ll.y = __float2bfloat16(v1 - __bfloat162float(hh.y));
                *(__nv_bfloat162*)(actH + o) = hh;
                *(__nv_bfloat162*)(actL + o) = ll;
            }
            if (m0g + 8 < M) {
                float v0 = acc[ni][2] + bv0, v1 = acc[ni][3] + bv1;
                size_t o = ((size_t)b * PPAD + out_off + m0g + 8) * 256 + n;
                __nv_bfloat162 hh, ll;
                hh.x = __float2bfloat16(v0);
                hh.y = __float2bfloat16(v1);
                ll.x = __float2bfloat16(v0 - __bfloat162float(hh.x));
                ll.y = __float2bfloat16(v1 - __bfloat162float(hh.y));
                *(__nv_bfloat162*)(actH + o) = hh;
                *(__nv_bfloat162*)(actL + o) = ll;
            }
        }
        cluster_sync_all();
    }
}

// ---------------- generic one-tile GEMM (for the x projection) ----------------
#define ROWB 528
#define ABUF (64 * ROWB)
#define SM_AH 0
#define SM_AL ABUF
#define SM_BH (2 * ABUF)
#define SM_BL (3 * ABUF)
#define P_SMEM (4 * ABUF)

__global__ void __launch_bounds__(128, 1)
gemm_mma(const uint4* __restrict__ Ahi, const uint4* __restrict__ Alo,
         const uint4* __restrict__ Bhi, const uint4* __restrict__ Blo,
         float* __restrict__ out, int a_rows, int out_ld) {
    extern __shared__ char sm[];
    int tid = threadIdx.x;
    int warp = tid >> 5, lane = tid & 31;
    int b = blockIdx.z, mt = blockIdx.x, nb = blockIdx.y * 64;

    {
        size_t srcb = ((size_t)b * a_rows + mt * 64) * 32;
#pragma unroll
        for (int i = 0; i < 16; i++) {
            int e = tid + 128 * i;
            int r = e >> 5, q = e & 31;
            int dst = r * ROWB + q * 16;
            *(uint4*)(sm + SM_AH + dst) = Ahi[srcb + (size_t)r * 32 + q];
            *(uint4*)(sm + SM_AL + dst) = Alo[srcb + (size_t)r * 32 + q];
        }
#pragma unroll
        for (int i = 0; i < 16; i++) {
            int e = tid + 128 * i;
            int r = e >> 5, q = e & 31;
            int dst = r * ROWB + q * 16;
            *(uint4*)(sm + SM_BH + dst) = Bhi[(size_t)(nb + r) * 32 + q];
            *(uint4*)(sm + SM_BL + dst) = Blo[(size_t)(nb + r) * 32 + q];
        }
    }
    __syncthreads();

    int g = lane >> 2, t = lane & 3;
    int ridx = lane & 15, half = lane >> 4;
    int wm = (warp >> 1) * 32;
    int wn = (warp & 1) * 32;
    uint32_t sbu = smem_u32(sm);

    uint32_t aoff0 = (wm + ridx) * ROWB + half * 16;
    uint32_t aoff1 = (wm + 16 + ridx) * ROWB + half * 16;
    uint32_t boff0 = (wn + ridx) * ROWB + half * 16;
    uint32_t boff1 = (wn + 16 + ridx) * ROWB + half * 16;

    float acc[2][4][4];
#pragma unroll
    for (int mi = 0; mi < 2; mi++)
#pragma unroll
        for (int ni = 0; ni < 4; ni++)
#pragma unroll
            for (int p = 0; p < 4; p++) acc[mi][ni][p] = 0.f;

#pragma unroll 1
    for (int pass = 0; pass < 3; pass++) {
        uint32_t Ab = sbu + ((pass == 2) ? SM_AL : SM_AH);
        uint32_t Bb = sbu + ((pass == 1) ? SM_BL : SM_BH);
#pragma unroll
        for (int ks = 0; ks < 16; ks++) {
            uint32_t o = ks * 32;
            uint32_t a0[4], a1[4];
            ldsm_x4(a0[0], a0[1], a0[2], a0[3], Ab + aoff0 + o);
            ldsm_x4(a1[0], a1[1], a1[2], a1[3], Ab + aoff1 + o);
            uint32_t p0, p1, p2, p3, q0, q1, q2, q3;
            ldsm_x4(p0, p1, p2, p3, Bb + boff0 + o);
            ldsm_x4(q0, q1, q2, q3, Bb + boff1 + o);
            uint32_t f0[2] = {p0, p2}, f1[2] = {p1, p3};
            uint32_t f2[2] = {q0, q2}, f3[2] = {q1, q3};
            mma_bf16(acc[0][0], a0, f0);
            mma_bf16(acc[0][1], a0, f1);
            mma_bf16(acc[0][2], a0, f2);
            mma_bf16(acc[0][3], a0, f3);
            mma_bf16(acc[1][0], a1, f0);
            mma_bf16(acc[1][1], a1, f1);
            mma_bf16(acc[1][2], a1, f2);
            mma_bf16(acc[1][3], a1, f3);
        }
    }

#pragma unroll
    for (int mi = 0; mi < 2; mi++) {
        int m = mt * 64 + wm + mi * 16 + g;
#pragma unroll
        for (int ni = 0; ni < 4; ni++) {
            int n = nb + wn + ni * 8 + 2 * t;
            float* p0 = out + ((size_t)b * a_rows + m) * out_ld + n;
            float* p1 = out + ((size_t)b * a_rows + m + 8) * out_ld + n;
            *(float2*)p0 = make_float2(acc[mi][ni][0], acc[mi][ni][1]);
            *(float2*)p1 = make_float2(acc[mi][ni][2], acc[mi][ni][3]);
        }
    }
}

// ---------------- Pc GEMM: A-resident, loop over 4 N-tiles, cp.async pipeline ----
#define PCW_SMEM (6 * ABUF)

__global__ void __launch_bounds__(128, 1)
pc_mma(const uint4* __restrict__ Ahi, const uint4* __restrict__ Alo,
       const uint4* __restrict__ Bhi, const uint4* __restrict__ Blo,
       float* __restrict__ Pc) {
    extern __shared__ char sm[];
    uint32_t sb = smem_u32(sm);
    const uint32_t A_H = sb, A_L = sb + ABUF;
    const uint32_t BH[2] = {sb + 2 * ABUF, sb + 4 * ABUF};
    const uint32_t BL[2] = {sb + 3 * ABUF, sb + 5 * ABUF};

    int tid = threadIdx.x;
    int warp = tid >> 5, lane = tid & 31;
    int b = blockIdx.z, mt = blockIdx.x;

    auto loadB = [&](int nt, int buf) {
#pragma unroll
        for (int i = 0; i < 16; i++) {
            int e = tid + 128 * i;
            int r = e >> 5, q = e & 31;
            uint32_t dst = r * ROWB + q * 16;
            cp16(BH[buf] + dst, &Bhi[(size_t)(nt * 64 + r) * 32 + q]);
            cp16(BL[buf] + dst, &Blo[(size_t)(nt * 64 + r) * 32 + q]);
        }
    };

    {
        size_t srcb = ((size_t)b * PPAD + mt * 64) * 32;
#pragma unroll
        for (int i = 0; i < 16; i++) {
            int e = tid + 128 * i;
            int r = e >> 5, q = e & 31;
            uint32_t dst = r * ROWB + q * 16;
            cp16(A_H + dst, &Ahi[srcb + (size_t)r * 32 + q]);
            cp16(A_L + dst, &Alo[srcb + (size_t)r * 32 + q]);
        }
    }
    loadB(0, 0);
    CP_COMMIT();
    loadB(1, 1);
    CP_COMMIT();

    int g = lane >> 2, t = lane & 3;
    int ridx = lane & 15, half = lane >> 4;
    int wm = (warp >> 1) * 32;
    int wn = (warp & 1) * 32;

    uint32_t aoff0 = (wm + ridx) * ROWB + half * 16;
    uint32_t aoff1 = (wm + 16 + ridx) * ROWB + half * 16;
    uint32_t boff0 = (wn + ridx) * ROWB + half * 16;
    uint32_t boff1 = (wn + 16 + ridx) * ROWB + half * 16;

#pragma unroll 1
    for (int nt = 0; nt < 4; nt++) {
        if (nt < 3) CP_WAIT1();
        else CP_WAIT0();
        __syncthreads();

        int buf = nt & 1;
        float acc[2][4][4];
#pragma unroll
        for (int mi = 0; mi < 2; mi++)
#pragma unroll
            for (int ni = 0; ni < 4; ni++)
#pragma unroll
                for (int p = 0; p < 4; p++) acc[mi][ni][p] = 0.f;

#pragma unroll 1
        for (int pass = 0; pass < 3; pass++) {
            uint32_t Ab = (pass == 2) ? A_L : A_H;
            uint32_t Bb = (pass == 1) ? BL[buf] : BH[buf];
#pragma unroll
            for (int ks = 0; ks < 16; ks++) {
                uint32_t o = ks * 32;
                uint32_t a0[4], a1[4];
                ldsm_x4(a0[0], a0[1], a0[2], a0[3], Ab + aoff0 + o);
                ldsm_x4(a1[0], a1[1], a1[2], a1[3], Ab + aoff1 + o);
                uint32_t p0, p1, p2, p3, q0, q1, q2, q3;
                ldsm_x4(p0, p1, p2, p3, Bb + boff0 + o);
                ldsm_x4(q0, q1, q2, q3, Bb + boff1 + o);
                uint32_t f0[2] = {p0, p2}, f1[2] = {p1, p3};
                uint32_t f2[2] = {q0, q2}, f3[2] = {q1, q3};
                mma_bf16(acc[0][0], a0, f0);
                mma_bf16(acc[0][1], a0, f1);
                mma_bf16(acc[0][2], a0, f2);
                mma_bf16(acc[0][3], a0, f3);
                mma_bf16(acc[1][0], a1, f0);
                mma_bf16(acc[1][1], a1, f1);
                mma_bf16(acc[1][2], a1, f2);
                mma_bf16(acc[1][3], a1, f3);
            }
        }
        __syncthreads();
        if (nt + 2 < 4) {
            loadB(nt + 2, buf);
            CP_COMMIT();
        }

        int nb = nt * 64;
#pragma unroll
        for (int mi = 0; mi < 2; mi++) {
            int m = mt * 64 + wm + mi * 16 + g;
#pragma unroll
            for (int ni = 0; ni < 4; ni++) {
                int n = nb + wn + ni * 8 + 2 * t;
                float* p0 = Pc + ((size_t)b * PPAD + m) * 256 + n;
                float* p1 = Pc + ((size_t)b * PPAD + m + 8) * 256 + n;
                *(float2*)p0 = make_float2(acc[mi][ni][0], acc[mi][ni][1]);
                *(float2*)p1 = make_float2(acc[mi][ni][2], acc[mi][ni][3]);
            }
        }
    }
}

// ---------------- final output assembly ----------------
__global__ void __launch_bounds__(256) final_out(
    const float* __restrict__ P, const float* __restrict__ Pc,
    const float* __restrict__ vis_b, float* __restrict__ out) {
    int i = blockIdx.x;
    int b = blockIdx.y;
    int o = threadIdx.x;

    __shared__ int lut[64];
    if (o < 64) {
        int j = o;
        int d = j - i;
        int pg = -1;
        if (d >= 1 && d <= 15) {
            pg = c_off[d - 1] + i;
        } else if (d >= 17 && d <= 31 && ((d - 17) & 1) == 0 && (i & 1) == 0) {
            pg = c_off[15 + ((d - 17) >> 1)] + (i >> 1);
        } else if (d >= 35 && d <= 63 && ((d - 35) & 3) == 0 && (i & 3) == 0) {
            pg = c_off[23 + ((d - 35) >> 2)] + (i >> 2);
        }
        lut[j] = pg;
    }
    __syncthreads();

    float vb = __ldg(vis_b + o);
    float p1 = P[((size_t)b * NG + i) * 768 + o];
    float p2x = P[((size_t)b * NG + i) * 768 + 256 + o];
    const float* P3b = P + (size_t)b * NG * 768 + 512 + o;
    const float* Pcb = Pc + (size_t)b * PPAD * 256 + o;

    float accr[64];
#pragma unroll
    for (int j = 0; j < 64; j++) {
        float v = vb;
        if (j == i) {
            v += p1 + p2x + P3b[(size_t)j * 768];
        } else {
            int pg = lut[j];
            if (pg >= 0) v += p1 + Pcb[(size_t)pg * 256] + P3b[(size_t)j * 768];
        }
        accr[j] = v;
    }

    float4* op = (float4*)(out + (((size_t)b * DCH + o) * NG + i) * NG);
#pragma unroll
    for (int q = 0; q < 16; q++)
        op[q] = make_float4(accr[4 * q], accr[4 * q + 1], accr[4 * q + 2], accr[4 * q + 3]);
}

// ---------------- host ----------------
extern "C" void kernel_launch(void* const* d_in, const int* in_sizes, int n_in,
                              void* d_out, int out_size) {
    const float* x  = (const float*)d_in[0];
    const float* w2 = (const float*)d_in[1];
    const float* b2 = (const float*)d_in[2];
    const float* w3 = (const float*)d_in[3];
    const float* b3 = (const float*)d_in[4];
    const float* vw = (const float*)d_in[5];
    const float* vb = (const float*)d_in[6];
    float* out = (float*)d_out;

    float *Pc, *P;
    uint4 *aH, *aL, *xH, *xL, *wH, *wL, *wbhi, *wblo;
    cudaGetSymbolAddress((void**)&Pc, g_Pc);
    cudaGetSymbolAddress((void**)&P, g_P);
    cudaGetSymbolAddress((void**)&aH, g_act_hi);
    cudaGetSymbolAddress((void**)&aL, g_act_lo);
    cudaGetSymbolAddress((void**)&xH, g_xa_hi);
    cudaGetSymbolAddress((void**)&xL, g_xa_lo);
    cudaGetSymbolAddress((void**)&wH, g_w_hi);
    cudaGetSymbolAddress((void**)&wL, g_w_lo);
    cudaGetSymbolAddress((void**)&wbhi, g_wB_hi);
    cudaGetSymbolAddress((void**)&wblo, g_wB_lo);

    cudaFuncSetAttribute(chain_mma, cudaFuncAttributeMaxDynamicSharedMemorySize,
                         CH_SMEM);
    cudaFuncSetAttribute(gemm_mma, cudaFuncAttributeMaxDynamicSharedMemorySize,
                         P_SMEM);
    cudaFuncSetAttribute(pc_mma, cudaFuncAttributeMaxDynamicSharedMemorySize,
                         PCW_SMEM);

    // fork/join side stream (no stream creation -> no device mem delta)
    cudaStream_t sp = cudaStreamPerThread;
    cudaEvent_t eF, eX, eW, eP;
    cudaEventCreateWithFlags(&eF, cudaEventDisableTiming);
    cudaEventCreateWithFlags(&eX, cudaEventDisableTiming);
    cudaEventCreateWithFlags(&eW, cudaEventDisableTiming);
    cudaEventCreateWithFlags(&eP, cudaEventDisableTiming);

    dim3 tb(32, 8);

    // fork: side stream handles xsplit and, later, the P projection
    cudaEventRecord(eF, 0);
    cudaStreamWaitEvent(sp, eF, 0);
    xsplit<<<dim3(2, 8, BATCH), tb, 0, sp>>>(x, (__nv_bfloat16*)xH,
                                             (__nv_bfloat16*)xL);
    cudaEventRecord(eX, sp);

    // main stream: weight splits
    wsplit<<<2048, 512>>>(w2, w3, vw, (__nv_bfloat16*)wH, (__nv_bfloat16*)wL,
                          (__nv_bfloat16*)wbhi, (__nv_bfloat16*)wblo);
    cudaEventRecord(eW, 0);

    // chain needs xsplit (side) + wsplit (program order)
    cudaStreamWaitEvent(0, eX, 0);
    chain_mma<<<128, 256, CH_SMEM>>>(xH, xL, wH, wL, b2, b3,
                                     (__nv_bfloat16*)aH, (__nv_bfloat16*)aL);

    // P projection on the side stream, concurrent with the chain
    cudaStreamWaitEvent(sp, eW, 0);
    gemm_mma<<<dim3(1, 12, BATCH), 128, P_SMEM, sp>>>(xH, xL, wbhi, wblo, P, 64,
                                                      768);
    cudaEventRecord(eP, sp);

    // Pc: depends on chain (main stream program order)
    pc_mma<<<dim3(PPAD / 64, 1, BATCH), 128, PCW_SMEM>>>(
        aH, aL, wbhi + 256 * 32, wblo + 256 * 32, Pc);

    // join: final_out needs P (side) + Pc (main)
    cudaStreamWaitEvent(0, eP, 0);
    final_out<<<dim3(NG, BATCH), 256>>>(P, Pc, vb, out);
}

// round 17
// speedup vs baseline: 1.0131x; 1.0131x over previous
#include <cuda_runtime.h>
#include <cuda_bf16.h>
#include <cstdint>
#include <cstddef>

#define BATCH 32
#define DCH 256
#define NG 64
#define PPAD 1088   // padded total conv positions (17 * 64)

__constant__ int c_off[31] = {0,64,128,192,252,312,372,432,488,544,600,656,708,760,812,
                              864,888,912,936,960,980,1000,1020,
                              1040,1048,1056,1064,1072,1076,1080,1084};
__constant__ int c_tb[31]  = {0,2,4,6,8,10,12,14,16,18,20,22,24,26,28, 30,
                              33,35,37,39,41,43,45, 47, 50,52,54,56,58,60,62};
__constant__ int c_taps[31] = {2,2,2,2,2,2,2,2,2,2,2,2,2,2,2, 3, 2,2,2,2,2,2,2, 3,
                               2,2,2,2,2,2,2};
__constant__ int c_cs[31]   = {1,1,1,1,1,1,1,1,1,1,1,1,1,1,1, 2, 1,1,1,1,1,1,1, 2,
                               1,1,1,1,1,1,1};
__constant__ int c_M[31]    = {63,62,61,60,59,58,57,56,55,54,53,52,51,50,49, 24,
                               23,22,21,20,19,18,17, 8, 7,6,5,4,3,2,1};
__constant__ int c_bi[31]   = {0,1,2,3,4,5,6,7,8,9,10,11,12,13,14, 0,
                               15,16,17,18,19,20,21, 1, 22,23,24,25,26,27,28};
__constant__ int c_isk3[31] = {0,0,0,0,0,0,0,0,0,0,0,0,0,0,0, 1, 0,0,0,0,0,0,0, 1,
                               0,0,0,0,0,0,0};
__constant__ int c_tb2[29]  = {0,2,4,6,8,10,12,14,16,18,20,22,24,26,28,
                               33,35,37,39,41,43,45, 50,52,54,56,58,60,62};

// ---------------- scratch ----------------
__device__ float g_Pc[(size_t)BATCH * PPAD * DCH];
__device__ float g_P[(size_t)BATCH * NG * 768];
__device__ uint4 g_act_hi[(size_t)BATCH * PPAD * 256 / 8];
__device__ uint4 g_act_lo[(size_t)BATCH * PPAD * 256 / 8];
__device__ uint4 g_xa_hi[(size_t)BATCH * 64 * 256 / 8];
__device__ uint4 g_xa_lo[(size_t)BATCH * 64 * 256 / 8];
__device__ uint4 g_w_hi[64 * 256 * 256 / 8];
__device__ uint4 g_w_lo[64 * 256 * 256 / 8];
__device__ uint4 g_wB_hi[768 * 256 / 8];
__device__ uint4 g_wB_lo[768 * 256 / 8];

// ---------------- helpers ----------------
__device__ __forceinline__ void cluster_sync_all() {
    asm volatile("barrier.cluster.arrive.aligned;" ::: "memory");
    asm volatile("barrier.cluster.wait.aligned;" ::: "memory");
}
__device__ __forceinline__ uint32_t smem_u32(const void* p) {
    uint32_t a;
    asm("{ .reg .u64 t; cvta.to.shared.u64 t, %1; cvt.u32.u64 %0, t; }"
        : "=r"(a) : "l"(p));
    return a;
}
__device__ __forceinline__ void mma_bf16(float* d, const uint32_t* a,
                                         const uint32_t* b) {
    asm volatile(
        "mma.sync.aligned.m16n8k16.row.col.f32.bf16.bf16.f32 "
        "{%0,%1,%2,%3}, {%4,%5,%6,%7}, {%8,%9}, {%0,%1,%2,%3};"
        : "+f"(d[0]), "+f"(d[1]), "+f"(d[2]), "+f"(d[3])
        : "r"(a[0]), "r"(a[1]), "r"(a[2]), "r"(a[3]), "r"(b[0]), "r"(b[1]));
}
__device__ __forceinline__ void ldsm_x4(uint32_t& r0, uint32_t& r1, uint32_t& r2,
                                        uint32_t& r3, uint32_t a) {
    asm volatile("ldmatrix.sync.aligned.m8n8.x4.shared.b16 {%0,%1,%2,%3}, [%4];"
                 : "=r"(r0), "=r"(r1), "=r"(r2), "=r"(r3) : "r"(a));
}
__device__ __forceinline__ void cp16(uint32_t s, const void* g) {
    asm volatile("cp.async.cg.shared.global [%0], [%1], 16;" :: "r"(s), "l"(g)
                 : "memory");
}
#define CP_COMMIT() asm volatile("cp.async.commit_group;" ::: "memory")
#define CP_WAIT0() asm volatile("cp.async.wait_group 0;" ::: "memory")
#define CP_WAIT1() asm volatile("cp.async.wait_group 1;" ::: "memory")

// ---------------- x -> xact split ----------------
__global__ void xsplit(const float* __restrict__ x,
                       __nv_bfloat16* __restrict__ hi,
                       __nv_bfloat16* __restrict__ lo) {
    __shared__ float t[32][33];
    int b = blockIdx.z;
    int p0 = blockIdx.x * 32, ch0 = blockIdx.y * 32;
    int tx = threadIdx.x, ty = threadIdx.y;
#pragma unroll
    for (int s = 0; s < 32; s += 8) {
        int c = ch0 + ty + s;
        t[ty + s][tx] = x[((size_t)b * DCH + c) * NG + p0 + tx];
    }
    __syncthreads();
#pragma unroll
    for (int s = 0; s < 32; s += 8) {
        int p = p0 + ty + s, c = ch0 + tx;
        float v = t[tx][ty + s];
        __nv_bfloat16 h = __float2bfloat16(v);
        __nv_bfloat16 l = __float2bfloat16(v - __bfloat162float(h));
        size_t o = ((size_t)b * NG + p) * 256 + c;
        hi[o] = h;
        lo[o] = l;
    }
}

// ---------------- weight split (w2/w3 per-tap + full vis_w merged) ----------------
#define W2TOT (29 * 256 * 256 * 2)
#define W3END (W2TOT + 2 * 256 * 256 * 3)
#define VWTOT (768 * 256)
#define PREP_TOT (W3END + VWTOT)
__global__ void wsplit(const float* __restrict__ w2, const float* __restrict__ w3,
                       const float* __restrict__ vw,
                       __nv_bfloat16* __restrict__ hi,
                       __nv_bfloat16* __restrict__ lo,
                       __nv_bfloat16* __restrict__ vhi,
                       __nv_bfloat16* __restrict__ vlo) {
    for (int idx = blockIdx.x * blockDim.x + threadIdx.x; idx < PREP_TOT;
         idx += gridDim.x * blockDim.x) {
        if (idx < W3END) {
            float v;
            int tap, n, c;
            if (idx < W2TOT) {
                int i2 = idx >> 17;
                int r = idx & 0x1FFFF;
                n = r >> 9;
                int r2 = r & 511;
                c = r2 >> 1;
                int kk = r2 & 1;
                v = w2[idx];
                tap = c_tb2[i2] + kk;
            } else {
                int j = idx - W2TOT;
                int i3 = j / 196608;
                int r = j % 196608;
                n = r / 768;
                int r2 = r % 768;
                c = r2 / 3;
                int kk = r2 % 3;
                v = w3[j];
                tap = (i3 ? 47 : 30) + kk;
            }
            size_t dst = (size_t)tap * 65536 + (size_t)n * 256 + c;
            __nv_bfloat16 h = __float2bfloat16(v);
            __nv_bfloat16 l = __float2bfloat16(v - __bfloat162float(h));
            hi[dst] = h;
            lo[dst] = l;
        } else {
            int j = idx - W3END;          // vis_w: row r = s*256+o, col c
            int r = j >> 8, c = j & 255;
            int o = r & 255, s = r >> 8;
            float v = vw[(size_t)o * 768 + s * 256 + c];
            __nv_bfloat16 h = __float2bfloat16(v);
            __nv_bfloat16 l = __float2bfloat16(v - __bfloat162float(h));
            vhi[(size_t)r * 256 + c] = h;
            vlo[(size_t)r * 256 + c] = l;
        }
    }
}

// ---------------- fused chain (R12 proven: 256 thr, 4-CTA cluster) ----------------
#define CROWB 528
#define CBUF (64 * CROWB)       // 33792 bytes
#define CH_SMEM (6 * CBUF)      // AH | AL | BH0 | BL0 | BH1 | BL1

__global__ void __launch_bounds__(256, 1) __cluster_dims__(4, 1, 1)
chain_mma(const uint4* __restrict__ xaH, const uint4* __restrict__ xaL,
          const uint4* __restrict__ gwH, const uint4* __restrict__ gwL,
          const float* __restrict__ b2, const float* __restrict__ b3,
          __nv_bfloat16* __restrict__ actH, __nv_bfloat16* __restrict__ actL) {
    extern __shared__ char sm[];
    uint32_t sb = smem_u32(sm);
    const uint32_t AHs = sb, ALs = sb + CBUF;
    const uint32_t BH0 = sb + 2 * CBUF, BL0 = sb + 3 * CBUF;
    const uint32_t BH1 = sb + 4 * CBUF, BL1 = sb + 5 * CBUF;

    int tid = threadIdx.x;
    int warp = tid >> 5, lane = tid & 31;
    int g = lane >> 2, t = lane & 3;
    int ridx = lane & 15, half = lane >> 4;
    int wm = (warp & 3) * 16;
    int wn = (warp >> 2) * 32;
    int b = blockIdx.x >> 2;
    int nblk = (blockIdx.x & 3) * 64;
    int lr = tid >> 5;
    int lq = tid & 31;

    const uint4* act4H = (const uint4*)actH;
    const uint4* act4L = (const uint4*)actL;

    uint32_t roff0 = (wn + ridx) * CROWB + half * 16;
    uint32_t roff1 = (wn + 16 + ridx) * CROWB + half * 16;

    auto load_B = [&](int tap, uint32_t BHb, uint32_t BLb) {
        size_t wb = (size_t)tap * 8192 + (size_t)nblk * 32;
#pragma unroll
        for (int i = 0; i < 8; i++) {
            int r = lr + 8 * i;
            uint32_t dst = r * CROWB + lq * 16;
            cp16(BHb + dst, &gwH[wb + (size_t)r * 32 + lq]);
            cp16(BLb + dst, &gwL[wb + (size_t)r * 32 + lq]);
        }
    };

    // preload layer-0 weights
    load_B(0, BH0, BL0);
    load_B(1, BH1, BL1);
    CP_COMMIT();

#pragma unroll 1
    for (int l = 0; l < 31; l++) {
        int taps = c_taps[l], cs = c_cs[l], tb = c_tb[l], M = c_M[l];
        int in_off = (l == 0) ? 0 : c_off[l - 1];
        int out_off = c_off[l];
        const float* bias = c_isk3[l] ? (b3 + c_bi[l] * 256) : (b2 + c_bi[l] * 256);

        if (l == 0) {
            size_t base = (size_t)b * 64 * 32;
#pragma unroll
            for (int i = 0; i < 8; i++) {
                int r = lr + 8 * i;
                uint32_t dst = r * CROWB + lq * 16;
                cp16(AHs + dst, &xaH[base + (size_t)r * 32 + lq]);
                cp16(ALs + dst, &xaL[base + (size_t)r * 32 + lq]);
            }
        } else {
#pragma unroll
            for (int i = 0; i < 8; i++) {
                int r = lr + 8 * i;
                int rr = in_off + r;
                if (rr > PPAD - 1) rr = PPAD - 1;
                size_t src = ((size_t)b * PPAD + rr) * 32 + lq;
                uint32_t dst = r * CROWB + lq * 16;
                cp16(AHs + dst, &act4H[src]);
                cp16(ALs + dst, &act4L[src]);
            }
        }
        CP_COMMIT();

        float acc[4][4];
#pragma unroll
        for (int ni = 0; ni < 4; ni++)
#pragma unroll
            for (int p = 0; p < 4; p++) acc[ni][p] = 0.f;

        bool active = (wm < M);

        auto mma_tap = [&](int tap, uint32_t BHb, uint32_t BLb) {
            int arow = ((wm + ridx) * cs + tap) & 63;
            uint32_t aHb = AHs + arow * CROWB + half * 16;
            uint32_t aLb = ALs + arow * CROWB + half * 16;
            uint32_t bh0 = BHb + roff0, bh1 = BHb + roff1;
            uint32_t bl0 = BLb + roff0, bl1 = BLb + roff1;
#pragma unroll
            for (int ks = 0; ks < 16; ks++) {
                uint32_t o = ks * 32;
                uint32_t ah[4], al[4];
                ldsm_x4(ah[0], ah[1], ah[2], ah[3], aHb + o);
                ldsm_x4(al[0], al[1], al[2], al[3], aLb + o);
                uint32_t p0, p1, p2, p3, q0, q1, q2, q3;
                ldsm_x4(p0, p1, p2, p3, bh0 + o);
                ldsm_x4(q0, q1, q2, q3, bh1 + o);
                uint32_t r0, r1, r2, r3, s0, s1, s2, s3;
                ldsm_x4(r0, r1, r2, r3, bl0 + o);
                ldsm_x4(s0, s1, s2, s3, bl1 + o);
                uint32_t fh0[2] = {p0, p2}, fh1[2] = {p1, p3};
                uint32_t fh2[2] = {q0, q2}, fh3[2] = {q1, q3};
                uint32_t fl0[2] = {r0, r2}, fl1[2] = {r1, r3};
                uint32_t fl2[2] = {s0, s2}, fl3[2] = {s1, s3};
                mma_bf16(acc[0], ah, fh0);
                mma_bf16(acc[1], ah, fh1);
                mma_bf16(acc[2], ah, fh2);
                mma_bf16(acc[3], ah, fh3);
                mma_bf16(acc[0], al, fh0);
                mma_bf16(acc[1], al, fh1);
                mma_bf16(acc[2], al, fh2);
                mma_bf16(acc[3], al, fh3);
                mma_bf16(acc[0], ah, fl0);
                mma_bf16(acc[1], ah, fl1);
                mma_bf16(acc[2], ah, fl2);
                mma_bf16(acc[3], ah, fl3);
            }
        };

        CP_WAIT0();
        __syncthreads();
        if (active) mma_tap(0, BH0, BL0);

        if (taps == 3) {
            __syncthreads();
            load_B(tb + 2, BH0, BL0);
            CP_COMMIT();
            if (active) mma_tap(1, BH1, BL1);
            CP_WAIT0();
            __syncthreads();
            if (active) mma_tap(2, BH0, BL0);
        } else {
            if (active) mma_tap(1, BH1, BL1);
        }

        __syncthreads();  // all B reads done -> buffers free
        if (l < 30) {     // prefetch next layer's weights (independent of sync)
            load_B(c_tb[l + 1], BH0, BL0);
            load_B(c_tb[l + 1] + 1, BH1, BL1);
            CP_COMMIT();
        }

        // epilogue
        int m0g = wm + g;
#pragma unroll
        for (int ni = 0; ni < 4; ni++) {
            int n = nblk + wn + ni * 8 + 2 * t;
            float bv0 = __ldg(bias + n);
            float bv1 = __ldg(bias + n + 1);
            if (m0g < M) {
                float v0 = acc[ni][0] + bv0, v1 = acc[ni][1] + bv1;
                size_t o = ((size_t)b * PPAD + out_off + m0g) * 256 + n;
                __nv_bfloat162 hh, ll;
                hh.x = __float2bfloat16(v0);
                hh.y = __float2bfloat16(v1);
                ll.x = __float2bfloat16(v0 - __bfloat162float(hh.x));
                ll.y = __float2bfloat16(v1 - __bfloat162float(hh.y));
                *(__nv_bfloat162*)(actH + o) = hh;
                *(__nv_bfloat162*)(actL + o) = ll;
            }
            if (m0g + 8 < M) {
                float v0 = acc[ni][2] + bv0, v1 = acc[ni][3] + bv1;
                size_t o = ((size_t)b * PPAD + out_off + m0g + 8) * 256 + n;
                __nv_bfloat162 hh, ll;
                hh.x = __float2bfloat16(v0);
                hh.y = __float2bfloat16(v1);
                ll.x = __float2bfloat16(v0 - __bfloat162float(hh.x));
                ll.y = __float2bfloat16(v1 - __bfloat162float(hh.y));
                *(__nv_bfloat162*)(actH + o) = hh;
                *(__nv_bfloat162*)(actL + o) = ll;
            }
        }
        cluster_sync_all();
    }
}

// ---------------- shared 256-thread warp-tile GEMM body pieces ----------------
#define ROWB 528
#define ABUF (64 * ROWB)

// per-warp m16 x n32 tile over one 64x64 block; merged hi/lo passes.
// A rows at Ab/ALb base; B at BHb/BLb. Accumulates into acc[4][4].
__device__ __forceinline__ void mma_block64(
    uint32_t AHb, uint32_t ALb, uint32_t BHb, uint32_t BLb,
    uint32_t aoff, uint32_t roff0, uint32_t roff1, float acc[4][4]) {
    uint32_t aH = AHb + aoff, aL = ALb + aoff;
    uint32_t bh0 = BHb + roff0, bh1 = BHb + roff1;
    uint32_t bl0 = BLb + roff0, bl1 = BLb + roff1;
#pragma unroll
    for (int ks = 0; ks < 16; ks++) {
        uint32_t o = ks * 32;
        uint32_t ah[4], al[4];
        ldsm_x4(ah[0], ah[1], ah[2], ah[3], aH + o);
        ldsm_x4(al[0], al[1], al[2], al[3], aL + o);
        uint32_t p0, p1, p2, p3, q0, q1, q2, q3;
        ldsm_x4(p0, p1, p2, p3, bh0 + o);
        ldsm_x4(q0, q1, q2, q3, bh1 + o);
        uint32_t r0, r1, r2, r3, s0, s1, s2, s3;
        ldsm_x4(r0, r1, r2, r3, bl0 + o);
        ldsm_x4(s0, s1, s2, s3, bl1 + o);
        uint32_t fh0[2] = {p0, p2}, fh1[2] = {p1, p3};
        uint32_t fh2[2] = {q0, q2}, fh3[2] = {q1, q3};
        uint32_t fl0[2] = {r0, r2}, fl1[2] = {r1, r3};
        uint32_t fl2[2] = {s0, s2}, fl3[2] = {s1, s3};
        mma_bf16(acc[0], ah, fh0);
        mma_bf16(acc[1], ah, fh1);
        mma_bf16(acc[2], ah, fh2);
        mma_bf16(acc[3], ah, fh3);
        mma_bf16(acc[0], al, fh0);
        mma_bf16(acc[1], al, fh1);
        mma_bf16(acc[2], al, fh2);
        mma_bf16(acc[3], al, fh3);
        mma_bf16(acc[0], ah, fl0);
        mma_bf16(acc[1], ah, fl1);
        mma_bf16(acc[2], ah, fl2);
        mma_bf16(acc[3], ah, fl3);
    }
}

// ---------------- P projection: one 64x64 tile per CTA, 256 threads ----------------
#define P_SMEM (4 * ABUF)

__global__ void __launch_bounds__(256, 1)
gemm_mma(const uint4* __restrict__ Ahi, const uint4* __restrict__ Alo,
         const uint4* __restrict__ Bhi, const uint4* __restrict__ Blo,
         float* __restrict__ out, int a_rows, int out_ld) {
    extern __shared__ char sm[];
    uint32_t sb = smem_u32(sm);
    const uint32_t A_H = sb, A_L = sb + ABUF;
    const uint32_t B_H = sb + 2 * ABUF, B_L = sb + 3 * ABUF;

    int tid = threadIdx.x;
    int warp = tid >> 5, lane = tid & 31;
    int b = blockIdx.z, mt = blockIdx.x, nb = blockIdx.y * 64;

    {
        size_t srcb = ((size_t)b * a_rows + mt * 64) * 32;
#pragma unroll
        for (int i = 0; i < 8; i++) {
            int e = tid + 256 * i;
            int r = e >> 5, q = e & 31;
            uint32_t dst = r * ROWB + q * 16;
            cp16(A_H + dst, &Ahi[srcb + (size_t)r * 32 + q]);
            cp16(A_L + dst, &Alo[srcb + (size_t)r * 32 + q]);
            cp16(B_H + dst, &Bhi[(size_t)(nb + r) * 32 + q]);
            cp16(B_L + dst, &Blo[(size_t)(nb + r) * 32 + q]);
        }
    }
    CP_COMMIT();
    CP_WAIT0();
    __syncthreads();

    int g = lane >> 2, t = lane & 3;
    int ridx = lane & 15, half = lane >> 4;
    int wm = (warp & 3) * 16;
    int wn = (warp >> 2) * 32;

    uint32_t aoff = (wm + ridx) * ROWB + half * 16;
    uint32_t roff0 = (wn + ridx) * ROWB + half * 16;
    uint32_t roff1 = (wn + 16 + ridx) * ROWB + half * 16;

    float acc[4][4];
#pragma unroll
    for (int ni = 0; ni < 4; ni++)
#pragma unroll
        for (int p = 0; p < 4; p++) acc[ni][p] = 0.f;

    mma_block64(A_H, A_L, B_H, B_L, aoff, roff0, roff1, acc);

    int m = mt * 64 + wm + g;
#pragma unroll
    for (int ni = 0; ni < 4; ni++) {
        int n = nb + wn + ni * 8 + 2 * t;
        float* p0 = out + ((size_t)b * a_rows + m) * out_ld + n;
        float* p1 = out + ((size_t)b * a_rows + m + 8) * out_ld + n;
        *(float2*)p0 = make_float2(acc[ni][0], acc[ni][1]);
        *(float2*)p1 = make_float2(acc[ni][2], acc[ni][3]);
    }
}

// ---------------- Pc GEMM: A-resident, 4 N-tiles, double-buffered B, 256 thr ----
#define PCW_SMEM (6 * ABUF)

__global__ void __launch_bounds__(256, 1)
pc_mma(const uint4* __restrict__ Ahi, const uint4* __restrict__ Alo,
       const uint4* __restrict__ Bhi, const uint4* __restrict__ Blo,
       float* __restrict__ Pc) {
    extern __shared__ char sm[];
    uint32_t sb = smem_u32(sm);
    const uint32_t A_H = sb, A_L = sb + ABUF;
    const uint32_t BH[2] = {sb + 2 * ABUF, sb + 4 * ABUF};
    const uint32_t BL[2] = {sb + 3 * ABUF, sb + 5 * ABUF};

    int tid = threadIdx.x;
    int warp = tid >> 5, lane = tid & 31;
    int b = blockIdx.z, mt = blockIdx.x;

    auto loadB = [&](int nt, int buf) {
#pragma unroll
        for (int i = 0; i < 8; i++) {
            int e = tid + 256 * i;
            int r = e >> 5, q = e & 31;
            uint32_t dst = r * ROWB + q * 16;
            cp16(BH[buf] + dst, &Bhi[(size_t)(nt * 64 + r) * 32 + q]);
            cp16(BL[buf] + dst, &Blo[(size_t)(nt * 64 + r) * 32 + q]);
        }
    };

    {
        size_t srcb = ((size_t)b * PPAD + mt * 64) * 32;
#pragma unroll
        for (int i = 0; i < 8; i++) {
            int e = tid + 256 * i;
            int r = e >> 5, q = e & 31;
            uint32_t dst = r * ROWB + q * 16;
            cp16(A_H + dst, &Ahi[srcb + (size_t)r * 32 + q]);
            cp16(A_L + dst, &Alo[srcb + (size_t)r * 32 + q]);
        }
    }
    loadB(0, 0);
    CP_COMMIT();
    loadB(1, 1);
    CP_COMMIT();

    int g = lane >> 2, t = lane & 3;
    int ridx = lane & 15, half = lane >> 4;
    int wm = (warp & 3) * 16;
    int wn = (warp >> 2) * 32;

    uint32_t aoff = (wm + ridx) * ROWB + half * 16;
    uint32_t roff0 = (wn + ridx) * ROWB + half * 16;
    uint32_t roff1 = (wn + 16 + ridx) * ROWB + half * 16;

#pragma unroll 1
    for (int nt = 0; nt < 4; nt++) {
        if (nt < 3) CP_WAIT1();
        else CP_WAIT0();
        __syncthreads();

        int buf = nt & 1;
        float acc[4][4];
#pragma unroll
        for (int ni = 0; ni < 4; ni++)
#pragma unroll
            for (int p = 0; p < 4; p++) acc[ni][p] = 0.f;

        mma_block64(A_H, A_L, BH[buf], BL[buf], aoff, roff0, roff1, acc);

        __syncthreads();
        if (nt + 2 < 4) {
            loadB(nt + 2, buf);
            CP_COMMIT();
        }

        int nb = nt * 64;
        int m = mt * 64 + wm + g;
#pragma unroll
        for (int ni = 0; ni < 4; ni++) {
            int n = nb + wn + ni * 8 + 2 * t;
            float* p0 = Pc + ((size_t)b * PPAD + m) * 256 + n;
            float* p1 = Pc + ((size_t)b * PPAD + m + 8) * 256 + n;
            *(float2*)p0 = make_float2(acc[ni][0], acc[ni][1]);
            *(float2*)p1 = make_float2(acc[ni][2], acc[ni][3]);
        }
    }
}

// ---------------- final output assembly ----------------
__global__ void __launch_bounds__(256) final_out(
    const float* __restrict__ P, const float* __restrict__ Pc,
    const float* __restrict__ vis_b, float* __restrict__ out) {
    int i = blockIdx.x;
    int b = blockIdx.y;
    int o = threadIdx.x;

    __shared__ int lut[64];
    if (o < 64) {
        int j = o;
        int d = j - i;
        int pg = -1;
        if (d >= 1 && d <= 15) {
            pg = c_off[d - 1] + i;
        } else if (d >= 17 && d <= 31 && ((d - 17) & 1) == 0 && (i & 1) == 0) {
            pg = c_off[15 + ((d - 17) >> 1)] + (i >> 1);
        } else if (d >= 35 && d <= 63 && ((d - 35) & 3) == 0 && (i & 3) == 0) {
            pg = c_off[23 + ((d - 35) >> 2)] + (i >> 2);
        }
        lut[j] = pg;
    }
    __syncthreads();

    float vb = __ldg(vis_b + o);
    float p1 = P[((size_t)b * NG + i) * 768 + o];
    float p2x = P[((size_t)b * NG + i) * 768 + 256 + o];
    const float* P3b = P + (size_t)b * NG * 768 + 512 + o;
    const float* Pcb = Pc + (size_t)b * PPAD * 256 + o;

    float accr[64];
#pragma unroll
    for (int j = 0; j < 64; j++) {
        float v = vb;
        if (j == i) {
            v += p1 + p2x + P3b[(size_t)j * 768];
        } else {
            int pg = lut[j];
            if (pg >= 0) v += p1 + Pcb[(size_t)pg * 256] + P3b[(size_t)j * 768];
        }
        accr[j] = v;
    }

    float4* op = (float4*)(out + (((size_t)b * DCH + o) * NG + i) * NG);
#pragma unroll
    for (int q = 0; q < 16; q++)
        op[q] = make_float4(accr[4 * q], accr[4 * q + 1], accr[4 * q + 2], accr[4 * q + 3]);
}

// ---------------- host ----------------
extern "C" void kernel_launch(void* const* d_in, const int* in_sizes, int n_in,
                              void* d_out, int out_size) {
    const float* x  = (const float*)d_in[0];
    const float* w2 = (const float*)d_in[1];
    const float* b2 = (const float*)d_in[2];
    const float* w3 = (const float*)d_in[3];
    const float* b3 = (const float*)d_in[4];
    const float* vw = (const float*)d_in[5];
    const float* vb = (const float*)d_in[6];
    float* out = (float*)d_out;

    float *Pc, *P;
    uint4 *aH, *aL, *xH, *xL, *wH, *wL, *wbhi, *wblo;
    cudaGetSymbolAddress((void**)&Pc, g_Pc);
    cudaGetSymbolAddress((void**)&P, g_P);
    cudaGetSymbolAddress((void**)&aH, g_act_hi);
    cudaGetSymbolAddress((void**)&aL, g_act_lo);
    cudaGetSymbolAddress((void**)&xH, g_xa_hi);
    cudaGetSymbolAddress((void**)&xL, g_xa_lo);
    cudaGetSymbolAddress((void**)&wH, g_w_hi);
    cudaGetSymbolAddress((void**)&wL, g_w_lo);
    cudaGetSymbolAddress((void**)&wbhi, g_wB_hi);
    cudaGetSymbolAddress((void**)&wblo, g_wB_lo);

    cudaFuncSetAttribute(chain_mma, cudaFuncAttributeMaxDynamicSharedMemorySize,
                         CH_SMEM);
    cudaFuncSetAttribute(gemm_mma, cudaFuncAttributeMaxDynamicSharedMemorySize,
                         P_SMEM);
    cudaFuncSetAttribute(pc_mma, cudaFuncAttributeMaxDynamicSharedMemorySize,
                         PCW_SMEM);

    dim3 tb(32, 8);
    wsplit<<<2048, 512>>>(w2, w3, vw, (__nv_bfloat16*)wH, (__nv_bfloat16*)wL,
                          (__nv_bfloat16*)wbhi, (__nv_bfloat16*)wblo);
    xsplit<<<dim3(2, 8, BATCH), tb>>>(x, (__nv_bfloat16*)xH, (__nv_bfloat16*)xL);

    // tensor-core chain (R12 proven): 32 clusters x 4 CTAs, 256 threads
    chain_mma<<<128, 256, CH_SMEM>>>(xH, xL, wH, wL, b2, b3,
                                     (__nv_bfloat16*)aH, (__nv_bfloat16*)aL);

    // merged x projections on tensor cores: P [B][64][768]
    gemm_mma<<<dim3(1, 12, BATCH), 256, P_SMEM>>>(xH, xL, wbhi, wblo, P, 64, 768);

    // Pc: A-resident, loops over 4 N-tiles (vis_w slice 1 = rows 256..511)
    pc_mma<<<dim3(PPAD / 64, 1, BATCH), 256, PCW_SMEM>>>(
        aH, aL, wbhi + 256 * 32, wblo + 256 * 32, Pc);

    final_out<<<dim3(NG, BATCH), 256>>>(P, Pc, vb, out);
}